// round 1
// baseline (speedup 1.0000x reference)
#include <cuda_runtime.h>
#include <math.h>

// Problem constants (from reference): q,k,v (B=4, D=1024, L=2048) fp32, H=8 heads,
// d_head = 128 for both qk and v. out (4, 1024, 2048) fp32. gamma scalar.
#define BB  4
#define HH  8
#define DD  1024
#define LL  2048
#define DH  128
#define BQ  64
#define BK  64
#define NT  256
#define NKT (LL / BK)   // 32 k-tiles

// Shared memory layout (floats):
//   sQ  : [DH][BQ]           = 8192   (Q tile, pre-scaled)
//   sKV : K: [DH][BK]=8192 / V: [BK][DH+1]=8256 (shared buffer)
//   sP  : [BQ][BK]           = 4096   (softmax probabilities)
//   smM/smL/smA : [BQ] each  = 192    (running max / sum / rescale alpha)
#define SQ_OFF   0
#define SKV_OFF  8192
#define SP_OFF   (SKV_OFF + 8256)
#define SM_OFF   (SP_OFF + 4096)
#define SL_OFF   (SM_OFF + BQ)
#define SA_OFF   (SL_OFF + BQ)
#define SMEM_FLOATS (SA_OFF + BQ)
#define SMEM_BYTES  (SMEM_FLOATS * 4)

// Thread mapping (256 threads):
//   tx = tid & 15, ty = tid >> 4
//   GEMM1 (S = Q^T K): thread owns s[4q][4k], q = 4*ty+qi, k = 4*tx+kj
//   GEMM2 (O += V P) : thread owns acc[8d][4q], d = tx+16*j, q = 4*ty+qi (same q ownership -> no stat transpose)
__global__ __launch_bounds__(NT, 2)
void attn_kernel(const float* __restrict__ qg, const float* __restrict__ kg,
                 const float* __restrict__ vg, const float* __restrict__ gamma,
                 float* __restrict__ out)
{
    extern __shared__ float smem[];
    float* sQ  = smem + SQ_OFF;
    float* sKV = smem + SKV_OFF;
    float* sP  = smem + SP_OFF;
    float* smM = smem + SM_OFF;
    float* smL = smem + SL_OFF;
    float* smA = smem + SA_OFF;

    const int tid = threadIdx.x;
    const int tx  = tid & 15;
    const int ty  = tid >> 4;

    const int qt = blockIdx.x;          // query tile index (0..31)
    const int bh = blockIdx.y;          // b*H + h       (0..31)
    const int b  = bh >> 3;
    const int h  = bh & 7;
    const size_t base = ((size_t)b * DD + (size_t)h * DH) * (size_t)LL;
    const float* qp = qg + base;
    const float* kp = kg + base;
    const float* vp = vg + base;
    const int q0 = qt * BQ;

    const float scale = rsqrtf((float)DH);

    // ---- load Q tile [DH][BQ], pre-scaled ----
    #pragma unroll
    for (int m = 0; m < 8; m++) {
        int d = ty + 16 * m;
        float4 t = *(const float4*)(qp + (size_t)d * LL + q0 + 4 * tx);
        t.x *= scale; t.y *= scale; t.z *= scale; t.w *= scale;
        *(float4*)(sQ + d * BQ + 4 * tx) = t;
    }
    if (tid < BQ) { smM[tid] = -3.0e38f; smL[tid] = 0.0f; }

    float acc[8][4];
    #pragma unroll
    for (int j = 0; j < 8; j++)
        #pragma unroll
        for (int qi = 0; qi < 4; qi++) acc[j][qi] = 0.0f;

    for (int t = 0; t < NKT; t++) {
        const int k0 = t * BK;

        __syncthreads();   // (A) prev GEMM2 done reading sKV/sP
        // ---- load K tile [DH][BK] ----
        #pragma unroll
        for (int m = 0; m < 8; m++) {
            int d = ty + 16 * m;
            float4 tt = *(const float4*)(kp + (size_t)d * LL + k0 + 4 * tx);
            *(float4*)(sKV + d * BK + 4 * tx) = tt;
        }
        __syncthreads();   // (B) K ready

        // ---- GEMM1: s[qi][kj] = sum_d Q[d][q] * K[d][k] ----
        float s[4][4];
        #pragma unroll
        for (int qi = 0; qi < 4; qi++)
            #pragma unroll
            for (int kj = 0; kj < 4; kj++) s[qi][kj] = 0.0f;

        #pragma unroll 4
        for (int d = 0; d < DH; d++) {
            float4 qv = *(const float4*)(sQ  + d * BQ + 4 * ty);
            float4 kv = *(const float4*)(sKV + d * BK + 4 * tx);
            s[0][0] = fmaf(qv.x, kv.x, s[0][0]);
            s[0][1] = fmaf(qv.x, kv.y, s[0][1]);
            s[0][2] = fmaf(qv.x, kv.z, s[0][2]);
            s[0][3] = fmaf(qv.x, kv.w, s[0][3]);
            s[1][0] = fmaf(qv.y, kv.x, s[1][0]);
            s[1][1] = fmaf(qv.y, kv.y, s[1][1]);
            s[1][2] = fmaf(qv.y, kv.z, s[1][2]);
            s[1][3] = fmaf(qv.y, kv.w, s[1][3]);
            s[2][0] = fmaf(qv.z, kv.x, s[2][0]);
            s[2][1] = fmaf(qv.z, kv.y, s[2][1]);
            s[2][2] = fmaf(qv.z, kv.z, s[2][2]);
            s[2][3] = fmaf(qv.z, kv.w, s[2][3]);
            s[3][0] = fmaf(qv.w, kv.x, s[3][0]);
            s[3][1] = fmaf(qv.w, kv.y, s[3][1]);
            s[3][2] = fmaf(qv.w, kv.z, s[3][2]);
            s[3][3] = fmaf(qv.w, kv.w, s[3][3]);
        }

        // ---- online softmax (row = query, spread over 16 lanes via tx) ----
        #pragma unroll
        for (int qi = 0; qi < 4; qi++) {
            const int qq = 4 * ty + qi;
            float rm = fmaxf(fmaxf(s[qi][0], s[qi][1]), fmaxf(s[qi][2], s[qi][3]));
            #pragma unroll
            for (int off = 8; off > 0; off >>= 1)
                rm = fmaxf(rm, __shfl_xor_sync(0xffffffffu, rm, off, 16));
            const float m_old = smM[qq];
            const float m_new = fmaxf(m_old, rm);
            float p0 = __expf(s[qi][0] - m_new);
            float p1 = __expf(s[qi][1] - m_new);
            float p2 = __expf(s[qi][2] - m_new);
            float p3 = __expf(s[qi][3] - m_new);
            float rs = (p0 + p1) + (p2 + p3);
            #pragma unroll
            for (int off = 8; off > 0; off >>= 1)
                rs += __shfl_xor_sync(0xffffffffu, rs, off, 16);
            if (tx == 0) {
                const float alpha = __expf(m_old - m_new);
                smA[qq] = alpha;
                smL[qq] = smL[qq] * alpha + rs;
                smM[qq] = m_new;
            }
            float4 pv4 = make_float4(p0, p1, p2, p3);
            *(float4*)(sP + qq * BK + 4 * tx) = pv4;
        }
        __syncthreads();   // (C) P + alpha ready; GEMM1 done reading sKV

        // ---- rescale accumulator by alpha[q] ----
        float al[4];
        #pragma unroll
        for (int qi = 0; qi < 4; qi++) al[qi] = smA[4 * ty + qi];
        #pragma unroll
        for (int j = 0; j < 8; j++)
            #pragma unroll
            for (int qi = 0; qi < 4; qi++) acc[j][qi] *= al[qi];

        // ---- load V tile transposed: sV[ki][d], stride 129 ----
        #pragma unroll
        for (int m = 0; m < 8; m++) {
            int d = ty + 16 * m;
            float4 tt = *(const float4*)(vp + (size_t)d * LL + k0 + 4 * tx);
            sKV[(4 * tx + 0) * 129 + d] = tt.x;
            sKV[(4 * tx + 1) * 129 + d] = tt.y;
            sKV[(4 * tx + 2) * 129 + d] = tt.z;
            sKV[(4 * tx + 3) * 129 + d] = tt.w;
        }
        __syncthreads();   // (D) V ready

        // ---- GEMM2: acc[d][q] += sum_ki V[ki][d] * P[q][ki] ----
        #pragma unroll 2
        for (int ki = 0; ki < BK; ki++) {
            float pvq[4];
            #pragma unroll
            for (int qi = 0; qi < 4; qi++)
                pvq[qi] = sP[(4 * ty + qi) * BK + ki];   // broadcast (2 ty per warp)
            #pragma unroll
            for (int j = 0; j < 8; j++) {
                float vv = sKV[ki * 129 + tx + 16 * j];  // conflict-free scalar
                #pragma unroll
                for (int qi = 0; qi < 4; qi++)
                    acc[j][qi] = fmaf(vv, pvq[qi], acc[j][qi]);
            }
        }
    }

    // ---- epilogue: O / l * gamma ----
    const float g = *gamma;
    float inv[4];
    #pragma unroll
    for (int qi = 0; qi < 4; qi++) inv[qi] = g / smL[4 * ty + qi];

    #pragma unroll
    for (int j = 0; j < 8; j++) {
        const int d = tx + 16 * j;
        float4 o;
        o.x = acc[j][0] * inv[0];
        o.y = acc[j][1] * inv[1];
        o.z = acc[j][2] * inv[2];
        o.w = acc[j][3] * inv[3];
        *(float4*)(out + base + (size_t)d * LL + q0 + 4 * ty) = o;
    }
}

extern "C" void kernel_launch(void* const* d_in, const int* in_sizes, int n_in,
                              void* d_out, int out_size)
{
    const float* q     = (const float*)d_in[0];
    const float* k     = (const float*)d_in[1];
    const float* v     = (const float*)d_in[2];
    const float* gamma = (const float*)d_in[3];
    float* out = (float*)d_out;

    // Opt-in to >48KB dynamic smem (idempotent, not a stream op — capture-safe).
    cudaFuncSetAttribute(attn_kernel, cudaFuncAttributeMaxDynamicSharedMemorySize, SMEM_BYTES);

    dim3 grid(LL / BQ, BB * HH);   // (32, 32) = 1024 CTAs
    attn_kernel<<<grid, NT, SMEM_BYTES>>>(q, k, v, gamma, out);
}

// round 2
// speedup vs baseline: 3.1491x; 3.1491x over previous
#include <cuda_runtime.h>

// MemoryNet attention: q,k,v (4, 1024, 2048) fp32 channels-first, 8 heads, d_head=128.
// out (4, 1024, 2048) fp32, gamma scalar.
#define LL   2048
#define DH   128
#define BQ   128
#define BK   64
#define NKT  (LL / BK)     // 32
#define NT   256           // 8 warps

// smem layout (floats)
#define QS_STRIDE 132      // Qs[q][d]   (q rows 128, d cols 128, pad->132)
#define KS_STRIDE 72       // Ks[d][k]   (d rows 128, k cols 64, pad->72)
#define VS_STRIDE 68       // Vs[d][ki]  (d rows 128, ki cols 64, pad->68)
#define PS_STRIDE 68       // Ps[q][ki]
#define QS_OFF  0
#define QS_SZ   (BQ * QS_STRIDE)          // 16896
#define KS_OFF  (QS_OFF + QS_SZ)
#define KS_SZ   (DH * KS_STRIDE)          // 9216 (x2 buffers)
#define VS_OFF  (KS_OFF + 2 * KS_SZ)
#define VS_SZ   (DH * VS_STRIDE)          // 8704
#define PS_OFF  (VS_OFF + VS_SZ)
#define PS_SZ   (BQ * PS_STRIDE)          // 8704
#define SMEM_FLOATS (PS_OFF + PS_SZ)      // 52736
#define SMEM_BYTES  (SMEM_FLOATS * 4)     // 210944 B

__device__ __forceinline__ unsigned f2tf(float f) {
    unsigned r;
    asm("cvt.rna.tf32.f32 %0, %1;" : "=r"(r) : "f"(f));
    return r;
}

__device__ __forceinline__ void mma_tf32(float c[4], unsigned a0, unsigned a1,
                                         unsigned a2, unsigned a3,
                                         unsigned b0, unsigned b1) {
    asm volatile(
        "mma.sync.aligned.m16n8k8.row.col.f32.tf32.tf32.f32 "
        "{%0,%1,%2,%3}, {%4,%5,%6,%7}, {%8,%9}, {%0,%1,%2,%3};"
        : "+f"(c[0]), "+f"(c[1]), "+f"(c[2]), "+f"(c[3])
        : "r"(a0), "r"(a1), "r"(a2), "r"(a3), "r"(b0), "r"(b1));
}

__device__ __forceinline__ void cp16(unsigned dst_smem, const void* src) {
    asm volatile("cp.async.cg.shared.global [%0], [%1], 16;" :: "r"(dst_smem), "l"(src));
}
__device__ __forceinline__ void cp_commit() {
    asm volatile("cp.async.commit_group;");
}
template <int N>
__device__ __forceinline__ void cp_wait() {
    asm volatile("cp.async.wait_group %0;" :: "n"(N));
}

__global__ __launch_bounds__(NT, 1)
void attn_kernel(const float* __restrict__ qg, const float* __restrict__ kg,
                 const float* __restrict__ vg, const float* __restrict__ gamma,
                 float* __restrict__ out)
{
    extern __shared__ float smem[];
    float* Qs = smem + QS_OFF;
    float* Vs = smem + VS_OFF;
    float* Ps = smem + PS_OFF;
    const unsigned smem_u32 = (unsigned)__cvta_generic_to_shared(smem);

    const int tid  = threadIdx.x;
    const int w    = tid >> 5;
    const int lane = tid & 31;
    const int g    = lane >> 2;   // groupID (0..7)
    const int tg   = lane & 3;    // thread-in-group
    const int qb   = w << 4;      // warp's q row base

    const int qt = blockIdx.x;              // 0..15
    const int bh = blockIdx.y;              // 0..31
    const size_t base = (size_t)bh * (DH * LL);
    const float* qp = qg + base;
    const float* kp = kg + base;
    const float* vp = vg + base;
    const int q0 = qt * BQ;

    const float scale = 0.08838834764831845f;   // 1/sqrt(128)

    // ---- load Q [d][L] -> Qs[q][d] transposed, scaled, tf32-rounded ----
    {
        const int dl = tid & 7;         // d lane 0..7
        const int q4 = tid >> 3;        // q quad 0..31
        #pragma unroll
        for (int m = 0; m < 16; m++) {
            const int d = dl + 8 * m;
            float4 t = *(const float4*)(qp + (size_t)d * LL + q0 + 4 * q4);
            Qs[(4 * q4 + 0) * QS_STRIDE + d] = __uint_as_float(f2tf(t.x * scale));
            Qs[(4 * q4 + 1) * QS_STRIDE + d] = __uint_as_float(f2tf(t.y * scale));
            Qs[(4 * q4 + 2) * QS_STRIDE + d] = __uint_as_float(f2tf(t.z * scale));
            Qs[(4 * q4 + 3) * QS_STRIDE + d] = __uint_as_float(f2tf(t.w * scale));
        }
    }

    // cp.async thread mapping for K/V tiles: [64 k][128 d] from gmem [d][L]
    const int kq = tid & 15;       // k quad: k = 4*kq
    const int dn = tid >> 4;       // d base: d = dn + 16*m

    // ---- prologue: issue K_0 ----
    #pragma unroll
    for (int m = 0; m < 8; m++) {
        const int d = dn + 16 * m;
        cp16(smem_u32 + (KS_OFF + d * KS_STRIDE + 4 * kq) * 4,
             kp + (size_t)d * LL + 0 + 4 * kq);
    }
    cp_commit();

    float o[16][4];
    #pragma unroll
    for (int nt = 0; nt < 16; nt++)
        #pragma unroll
        for (int i = 0; i < 4; i++) o[nt][i] = 0.0f;

    float m0 = -3.0e38f, m1 = -3.0e38f;   // running max, rows r0=qb+g, r1=qb+g+8
    float l0 = 0.0f, l1 = 0.0f;           // running denom

    for (int t = 0; t < NKT; t++) {
        const int k0 = t * BK;
        const float* Ksb = smem + KS_OFF + (t & 1) * KS_SZ;

        __syncthreads();   // (A) GEMM2_{t-1} done: Vs & Ps free

        // ---- issue V_t ----
        #pragma unroll
        for (int m = 0; m < 8; m++) {
            const int d = dn + 16 * m;
            cp16(smem_u32 + (VS_OFF + d * VS_STRIDE + 4 * kq) * 4,
                 vp + (size_t)d * LL + k0 + 4 * kq);
        }
        cp_commit();

        cp_wait<1>();      // K_t landed (V_t may pend)
        __syncthreads();   // (B) K_t visible CTA-wide

        // ---- GEMM1: S[16q][64k] = Q·K^T ----
        float s[8][4];
        #pragma unroll
        for (int nt = 0; nt < 8; nt++)
            #pragma unroll
            for (int i = 0; i < 4; i++) s[nt][i] = 0.0f;

        #pragma unroll 4
        for (int kk = 0; kk < 16; kk++) {
            const int d0 = kk * 8;
            const float* qrow = Qs + (qb + g) * QS_STRIDE + d0 + tg;
            const unsigned a0 = __float_as_uint(qrow[0]);
            const unsigned a2 = __float_as_uint(qrow[4]);
            const unsigned a1 = __float_as_uint(qrow[8 * QS_STRIDE]);
            const unsigned a3 = __float_as_uint(qrow[8 * QS_STRIDE + 4]);
            const float* kcol = Ksb + (d0 + tg) * KS_STRIDE + g;
            #pragma unroll
            for (int nt = 0; nt < 8; nt++) {
                const unsigned b0 = f2tf(kcol[8 * nt]);
                const unsigned b1 = f2tf(kcol[4 * KS_STRIDE + 8 * nt]);
                mma_tf32(s[nt], a0, a1, a2, a3, b0, b1);
            }
        }

        // ---- issue K_{t+1} (wraps at end: harmless dummy reload) ----
        {
            const int tn = (t + 1) & (NKT - 1);
            const int kn0 = tn * BK;
            const unsigned kboff = KS_OFF + ((t + 1) & 1) * KS_SZ;
            #pragma unroll
            for (int m = 0; m < 8; m++) {
                const int d = dn + 16 * m;
                cp16(smem_u32 + (kboff + d * KS_STRIDE + 4 * kq) * 4,
                     kp + (size_t)d * LL + kn0 + 4 * kq);
            }
            cp_commit();
        }

        // ---- online softmax (rows r0, r1 fully owned by this warp's 4-lane groups) ----
        {
            float tm0 = -3.0e38f, tm1 = -3.0e38f;
            #pragma unroll
            for (int nt = 0; nt < 8; nt++) {
                tm0 = fmaxf(tm0, fmaxf(s[nt][0], s[nt][1]));
                tm1 = fmaxf(tm1, fmaxf(s[nt][2], s[nt][3]));
            }
            tm0 = fmaxf(tm0, __shfl_xor_sync(0xffffffffu, tm0, 1));
            tm0 = fmaxf(tm0, __shfl_xor_sync(0xffffffffu, tm0, 2));
            tm1 = fmaxf(tm1, __shfl_xor_sync(0xffffffffu, tm1, 1));
            tm1 = fmaxf(tm1, __shfl_xor_sync(0xffffffffu, tm1, 2));
            const float mn0 = fmaxf(m0, tm0);
            const float mn1 = fmaxf(m1, tm1);
            const float al0 = __expf(m0 - mn0);
            const float al1 = __expf(m1 - mn1);
            float sum0 = 0.0f, sum1 = 0.0f;
            float* pr0 = Ps + (qb + g) * PS_STRIDE + 2 * tg;
            float* pr1 = pr0 + 8 * PS_STRIDE;
            #pragma unroll
            for (int nt = 0; nt < 8; nt++) {
                const float p00 = __expf(s[nt][0] - mn0);
                const float p01 = __expf(s[nt][1] - mn0);
                const float p10 = __expf(s[nt][2] - mn1);
                const float p11 = __expf(s[nt][3] - mn1);
                sum0 += p00 + p01;
                sum1 += p10 + p11;
                pr0[8 * nt]     = __uint_as_float(f2tf(p00));
                pr0[8 * nt + 1] = __uint_as_float(f2tf(p01));
                pr1[8 * nt]     = __uint_as_float(f2tf(p10));
                pr1[8 * nt + 1] = __uint_as_float(f2tf(p11));
            }
            sum0 += __shfl_xor_sync(0xffffffffu, sum0, 1);
            sum0 += __shfl_xor_sync(0xffffffffu, sum0, 2);
            sum1 += __shfl_xor_sync(0xffffffffu, sum1, 1);
            sum1 += __shfl_xor_sync(0xffffffffu, sum1, 2);
            l0 = l0 * al0 + sum0;
            l1 = l1 * al1 + sum1;
            m0 = mn0; m1 = mn1;
            // rescale O accumulators
            #pragma unroll
            for (int nt = 0; nt < 16; nt++) {
                o[nt][0] *= al0; o[nt][1] *= al0;
                o[nt][2] *= al1; o[nt][3] *= al1;
            }
        }

        cp_wait<1>();      // V_t landed (K_{t+1} may pend)
        __syncthreads();   // (C) V_t visible

        // ---- GEMM2: O[16q][128d] += P·V ----
        #pragma unroll 2
        for (int kk = 0; kk < 8; kk++) {
            const int ki0 = kk * 8;
            const float* prow = Ps + (qb + g) * PS_STRIDE + ki0 + tg;
            const unsigned a0 = __float_as_uint(prow[0]);
            const unsigned a2 = __float_as_uint(prow[4]);
            const unsigned a1 = __float_as_uint(prow[8 * PS_STRIDE]);
            const unsigned a3 = __float_as_uint(prow[8 * PS_STRIDE + 4]);
            #pragma unroll
            for (int nt = 0; nt < 16; nt++) {
                const float* vcol = Vs + (8 * nt + g) * VS_STRIDE + ki0 + tg;
                const unsigned b0 = f2tf(vcol[0]);
                const unsigned b1 = f2tf(vcol[4]);
                mma_tf32(o[nt], a0, a1, a2, a3, b0, b1);
            }
        }
    }

    // ---- epilogue: O/l * gamma, transpose through smem (reuse Qs), coalesced store ----
    const float gm = *gamma;
    const float inv0 = gm / l0;
    const float inv1 = gm / l1;

    __syncthreads();
    float* sOut = Qs;   // [d][q], stride QS_STRIDE
    #pragma unroll
    for (int nt = 0; nt < 16; nt++) {
        const int d0 = 8 * nt + 2 * tg;
        sOut[(d0    ) * QS_STRIDE + qb + g    ] = o[nt][0] * inv0;
        sOut[(d0 + 1) * QS_STRIDE + qb + g    ] = o[nt][1] * inv0;
        sOut[(d0    ) * QS_STRIDE + qb + g + 8] = o[nt][2] * inv1;
        sOut[(d0 + 1) * QS_STRIDE + qb + g + 8] = o[nt][3] * inv1;
    }
    __syncthreads();

    #pragma unroll
    for (int it = 0; it < 16; it++) {
        const int idx = tid + NT * it;     // 4096 float4s = 128d x 32 quads
        const int d  = idx >> 5;
        const int qv = idx & 31;
        float4 tt = *(const float4*)(sOut + d * QS_STRIDE + 4 * qv);
        *(float4*)(out + base + (size_t)d * LL + q0 + 4 * qv) = tt;
    }
}

extern "C" void kernel_launch(void* const* d_in, const int* in_sizes, int n_in,
                              void* d_out, int out_size)
{
    const float* q     = (const float*)d_in[0];
    const float* k     = (const float*)d_in[1];
    const float* v     = (const float*)d_in[2];
    const float* gamma = (const float*)d_in[3];
    float* out = (float*)d_out;

    cudaFuncSetAttribute(attn_kernel, cudaFuncAttributeMaxDynamicSharedMemorySize, SMEM_BYTES);

    dim3 grid(LL / BQ, 32);    // 16 q-tiles x (4 batch * 8 heads) = 512 CTAs
    attn_kernel<<<grid, NT, SMEM_BYTES>>>(q, k, v, gamma, out);
}